// round 16
// baseline (speedup 1.0000x reference)
#include <cuda_runtime.h>
#include <cuda_bf16.h>
#include <cstdint>

// Hamming1Layer v13: v10 (best, 76.3us) with TILE_L=1024 -> only 4 remote bits.
// y[b,c,l] = (w_self*x[b,c,l] + sum_k w_bits[k]*x[b,c,l^(1<<k)]) / 15
// out[b,o,l] = sum_c mix_w[o,c]*y[b,c,l] + mix_b[o]
// B=32, C_IN=32, C_OUT=64, L=16384, N_BITS=14.
//
// v13 vs v10: bit 9 moves in-tile (bf16 SMEM), remote = bits 10..13 only:
// per gather item -1 LDG.128 / -1 L2-latency dep, +1 LDS.uint2. Grid halves
// to 512 blocks (block-fixed staging cost halves). All other structure
// byte-identical to v10. Split MMA: D = Wh.Yh + Wh.Yl + Wl.Yh.

#define NBITS   14
#define LPOW    16384
#define CIN     32
#define COUT    64
#define TILE_L  1024
#define CHUNK_L 128
#define NCHUNK  (TILE_L / CHUNK_L)     // 8
#define CQUADS  (CHUNK_L / 4)          // 32
#define TPB     256

// ---- smem map (bytes) ----
#define YROW    136                    // bf16 elems per y row (128 + 8 pad)
#define WROW    40                     // bf16 elems per W row (32 + 8 pad)
#define YSPLIT  (CIN * YROW * 2)       // 8704
#define YBUF    (2 * YSPLIT)           // h + l planes = 17408
#define SMEM_XB    0                   // bf16 [CIN][TILE_L]       = 65536
#define SMEM_Y     65536               // [2 buf][h/l][CIN][YROW]  = 34816
#define SMEM_WH    100352              // bf16 [COUT][WROW] = 5120
#define SMEM_WL    105472              // bf16 [COUT][WROW] = 5120
#define SMEM_BIAS  110592              // f32 [COUT] = 256
#define SMEM_TOTAL 110848              // x2 = 221.7KB <= 228KB -> 2 blocks/SM

__device__ __forceinline__ uint64_t pack2(float lo, float hi) {
    uint64_t r; asm("mov.b64 %0, {%1, %2};" : "=l"(r) : "f"(lo), "f"(hi)); return r;
}
__device__ __forceinline__ void unpack2(uint64_t v, float& lo, float& hi) {
    asm("mov.b64 {%0, %1}, %2;" : "=f"(lo), "=f"(hi) : "l"(v));
}
__device__ __forceinline__ uint64_t fma2(uint64_t a, uint64_t b, uint64_t c) {
    uint64_t d; asm("fma.rn.f32x2 %0, %1, %2, %3;" : "=l"(d) : "l"(a), "l"(b), "l"(c)); return d;
}
__device__ __forceinline__ uint64_t mul2(uint64_t a, uint64_t b) {
    uint64_t d; asm("mul.rn.f32x2 %0, %1, %2;" : "=l"(d) : "l"(a), "l"(b)); return d;
}
__device__ __forceinline__ uint64_t add2(uint64_t a, uint64_t b) {
    uint64_t d; asm("add.rn.f32x2 %0, %1, %2;" : "=l"(d) : "l"(a), "l"(b)); return d;
}
__device__ __forceinline__ uint64_t sub2(uint64_t a, uint64_t b) {
    uint64_t d; asm("sub.rn.f32x2 %0, %1, %2;" : "=l"(d) : "l"(a), "l"(b)); return d;
}
__device__ __forceinline__ uint64_t bfp_to_f32x2(uint32_t v) {
    uint32_t lo = v << 16, hi = v & 0xFFFF0000u;
    uint64_t r; asm("mov.b64 %0, {%1, %2};" : "=l"(r) : "r"(lo), "r"(hi)); return r;
}
__device__ __forceinline__ uint32_t f2_to_bfp(float a, float b) {
    uint32_t r; asm("cvt.rn.bf16x2.f32 %0, %1, %2;" : "=r"(r) : "f"(b), "f"(a)); return r;
}

#define LDSM_X4_T(d, addr)                                                      \
    asm volatile("ldmatrix.sync.aligned.m8n8.x4.trans.shared.b16 "              \
                 "{%0,%1,%2,%3}, [%4];"                                         \
                 : "=r"((d)[0]), "=r"((d)[1]), "=r"((d)[2]), "=r"((d)[3])       \
                 : "r"(addr))
#define LDSM_X2(d0, d1, addr)                                                   \
    asm volatile("ldmatrix.sync.aligned.m8n8.x2.shared.b16 {%0,%1}, [%2];"      \
                 : "=r"(d0), "=r"(d1) : "r"(addr))
#define MMA_BF16(c, a, b0, b1)                                                  \
    asm volatile("mma.sync.aligned.m16n8k16.row.col.f32.bf16.bf16.f32 "         \
                 "{%0,%1,%2,%3}, {%4,%5,%6,%7}, {%8,%9}, {%0,%1,%2,%3};"        \
                 : "+f"((c)[0]), "+f"((c)[1]), "+f"((c)[2]), "+f"((c)[3])       \
                 : "r"((a)[0]), "r"((a)[1]), "r"((a)[2]), "r"((a)[3]),          \
                   "r"(b0), "r"(b1))

extern __shared__ unsigned char smem_raw[];

__global__ __launch_bounds__(TPB, 2)
void hamming_kernel(const float* __restrict__ x,
                    const float* __restrict__ w_self,
                    const float* __restrict__ w_bits,
                    const float* __restrict__ mix_w,
                    const float* __restrict__ mix_b,
                    float* __restrict__ out)
{
    uint32_t*      sh_xb   = (uint32_t*)(smem_raw + SMEM_XB);
    __nv_bfloat16* sh_wh   = (__nv_bfloat16*)(smem_raw + SMEM_WH);
    __nv_bfloat16* sh_wl   = (__nv_bfloat16*)(smem_raw + SMEM_WL);
    float*         sh_bias = (float*)(smem_raw + SMEM_BIAS);
    const uint32_t sbase   = (uint32_t)__cvta_generic_to_shared(smem_raw);

    const int tid   = threadIdx.x;
    const int wid   = tid >> 5;
    const int lane  = tid & 31;
    const int tile  = blockIdx.x;            // 0..15
    const int b     = blockIdx.y;            // 0..31
    const int lbase = tile * TILE_L;

    // ---- cooperative staging ----
    const float inv15 = 1.0f / 15.0f;
    for (int e = tid; e < CIN * COUT; e += TPB) {   // e = o*32 + c
        int o = e >> 5, c = e & 31;
        float w = mix_w[e] * inv15;
        __nv_bfloat16 wh = __float2bfloat16(w);
        sh_wh[o * WROW + c] = wh;
        sh_wl[o * WROW + c] = __float2bfloat16(w - __bfloat162float(wh));
    }
    if (tid < COUT) sh_bias[tid] = mix_b[tid];

    const float4* xg4 = (const float4*)(x + (size_t)b * CIN * LPOW);
    #pragma unroll
    for (int i = 0; i < (CIN * TILE_L / 4) / TPB; ++i) {    // 32 iters
        int j  = i * TPB + tid;
        int c  = j >> 8;                 // TILE_L/4 = 256 float4 per c
        int lw = j & 255;
        float4 f = xg4[(size_t)c * (LPOW / 4) + (lbase >> 2) + lw];
        uint2 p; p.x = f2_to_bfp(f.x, f.y); p.y = f2_to_bfp(f.z, f.w);
        *(uint2*)(sh_xb + c * (TILE_L / 2) + lw * 2) = p;
    }

    // ---- per-thread gather weights ----
    const float ws = *w_self;
    const uint64_t ws2 = pack2(ws, ws);
    uint64_t wb2[NBITS];
    #pragma unroll
    for (int k = 0; k < NBITS; ++k) { float v = w_bits[k]; wb2[k] = pack2(v, v); }

    // ---- mix-stage lane constants ----
    const int g = lane >> 2, t = lane & 3;
    const int wbase = wid * 16;
    const int krow0 = (lane & 7) + ((lane >> 4) & 1) * 8;
    const int mcolA = ((lane >> 3) & 1) * 8;
    const int brow  = lane & 7;
    const int bk    = ((lane >> 3) & 1) * 8;
    const uint32_t whB = sbase + SMEM_WH;
    const uint32_t wlB = sbase + SMEM_WL;

    const float* xb = x + (size_t)b * CIN * LPOW;
    float* og = out + (size_t)b * COUT * LPOW;

    __syncthreads();

    for (int ck = 0; ck < NCHUNK; ++ck) {
        // ================= gather (all 256 threads) =================
        unsigned char* ybh_w = smem_raw + SMEM_Y + (ck & 1) * YBUF;
        unsigned char* ybl_w = ybh_w + YSPLIT;

        #pragma unroll
        for (int it = 0; it < (CIN * CQUADS) / TPB; ++it) {   // 4 iters
            int idx = it * TPB + tid;
            int c   = idx >> 5;              // 0..31
            int ql  = idx & 31;              // quad in chunk
            int qg  = ck * CQUADS + ql;      // quad in tile [0,256)

            const float4*   xc4 = (const float4*)(xb + (size_t)c * LPOW);
            const uint32_t* row = sh_xb + c * (TILE_L / 2);

            // remote (L2-latency) loads first; L1-hot self last
            float4 g10 = xc4[((lbase ^ (1 << 10)) >> 2) + qg];
            float4 g11 = xc4[((lbase ^ (1 << 11)) >> 2) + qg];
            float4 g12 = xc4[((lbase ^ (1 << 12)) >> 2) + qg];
            float4 g13 = xc4[((lbase ^ (1 << 13)) >> 2) + qg];
            float4 s   = xc4[(lbase >> 2) + qg];

            uint64_t s01 = pack2(s.x, s.y), s23 = pack2(s.z, s.w);
            uint64_t a01 = mul2(ws2, s01);
            uint64_t a23 = mul2(ws2, s23);
            a01 = fma2(wb2[0], pack2(s.y, s.x), a01);
            a23 = fma2(wb2[0], pack2(s.w, s.z), a23);
            a01 = fma2(wb2[1], s23, a01);
            a23 = fma2(wb2[1], s01, a23);

            // bits 2..9: bf16 quads from SMEM tile
            uint64_t b01, b23;
            {
                uint2 n = *(const uint2*)(row + (qg ^ 1) * 2);
                b01 = mul2(wb2[2], bfp_to_f32x2(n.x));
                b23 = mul2(wb2[2], bfp_to_f32x2(n.y));
            }
            #pragma unroll
            for (int k = 3; k <= 9; ++k) {
                int qn = qg ^ (1 << (k - 2));
                uint2 n = *(const uint2*)(row + qn * 2);
                b01 = fma2(wb2[k], bfp_to_f32x2(n.x), b01);
                b23 = fma2(wb2[k], bfp_to_f32x2(n.y), b23);
            }

            // bits 10..13: f32 quads from global (L2-hot)
            a01 = fma2(wb2[10], pack2(g10.x, g10.y), a01);
            a23 = fma2(wb2[10], pack2(g10.z, g10.w), a23);
            a01 = fma2(wb2[11], pack2(g11.x, g11.y), a01);
            a23 = fma2(wb2[11], pack2(g11.z, g11.w), a23);
            a01 = fma2(wb2[12], pack2(g12.x, g12.y), a01);
            a23 = fma2(wb2[12], pack2(g12.z, g12.w), a23);
            a01 = fma2(wb2[13], pack2(g13.x, g13.y), a01);
            a23 = fma2(wb2[13], pack2(g13.z, g13.w), a23);

            a01 = add2(a01, b01);
            a23 = add2(a23, b23);

            // split y -> bf16 hi/lo planes, layout [c][l] padded to YROW
            float y0, y1, y2, y3;
            unpack2(a01, y0, y1);
            unpack2(a23, y2, y3);
            uint32_t hA = f2_to_bfp(y0, y1);
            uint32_t hB = f2_to_bfp(y2, y3);
            uint64_t r01 = sub2(a01, bfp_to_f32x2(hA));
            uint64_t r23 = sub2(a23, bfp_to_f32x2(hB));
            float r0, r1, r2, r3;
            unpack2(r01, r0, r1);
            unpack2(r23, r2, r3);
            uint32_t lA = f2_to_bfp(r0, r1);
            uint32_t lB = f2_to_bfp(r2, r3);

            int yoff = c * (YROW * 2) + ql * 8;      // bytes
            *(uint2*)(ybh_w + yoff) = make_uint2(hA, hB);
            *(uint2*)(ybl_w + yoff) = make_uint2(lA, lB);
        }
        __syncthreads();    // chunk ck y ready; mixing of ck-1 finished

        // ================= mix (all 8 warps, one m16 tile each) =================
        const uint32_t ybh = sbase + SMEM_Y + (ck & 1) * YBUF;
        const uint32_t ybl = ybh + YSPLIT;

        uint32_t Ah[2][4], Al[2][4];
        #pragma unroll
        for (int ks = 0; ks < 2; ++ks) {
            uint32_t off = (uint32_t)(((ks * 16 + krow0) * YROW + wbase + mcolA) * 2);
            LDSM_X4_T(Ah[ks], ybh + off);
            LDSM_X4_T(Al[ks], ybl + off);
        }

        float acc[8][4];
        #pragma unroll
        for (int nt = 0; nt < 8; ++nt) {
            float2 bb = *(float2*)(sh_bias + nt * 8 + 2 * t);
            acc[nt][0] = bb.x; acc[nt][1] = bb.y;
            acc[nt][2] = bb.x; acc[nt][3] = bb.y;
        }

        #pragma unroll
        for (int ks = 0; ks < 2; ++ks) {
            #pragma unroll
            for (int nt = 0; nt < 8; ++nt) {
                uint32_t woff = (uint32_t)(((nt * 8 + brow) * WROW + ks * 16 + bk) * 2);
                uint32_t bh0, bh1, bl0, bl1;
                LDSM_X2(bh0, bh1, whB + woff);
                MMA_BF16(acc[nt], Ah[ks], bh0, bh1);   // Wh.Yh
                MMA_BF16(acc[nt], Al[ks], bh0, bh1);   // Wh.Yl
                LDSM_X2(bl0, bl1, wlB + woff);
                MMA_BF16(acc[nt], Ah[ks], bl0, bl1);   // Wl.Yh
            }
        }

        // epilogue: D[m=l][n=o] -> out[b][o][l]; c2/c3 live at row m+8
        const int l0 = lbase + ck * CHUNK_L + wbase + g;
        #pragma unroll
        for (int nt = 0; nt < 8; ++nt) {
            int o0 = nt * 8 + 2 * t;
            og[(size_t)o0 * LPOW + l0]            = acc[nt][0];
            og[(size_t)(o0 + 1) * LPOW + l0]      = acc[nt][1];
            og[(size_t)o0 * LPOW + l0 + 8]        = acc[nt][2];
            og[(size_t)(o0 + 1) * LPOW + l0 + 8]  = acc[nt][3];
        }
    }
}

extern "C" void kernel_launch(void* const* d_in, const int* in_sizes, int n_in,
                              void* d_out, int out_size)
{
    const float* x      = (const float*)d_in[0];
    const float* w_self = (const float*)d_in[1];
    const float* w_bits = (const float*)d_in[2];
    const float* mix_w  = (const float*)d_in[3];
    const float* mix_b  = (const float*)d_in[4];
    float* out = (float*)d_out;

    cudaFuncSetAttribute(hamming_kernel,
                         cudaFuncAttributeMaxDynamicSharedMemorySize, SMEM_TOTAL);

    dim3 grid(LPOW / TILE_L, 32, 1);   // (16 tiles, 32 batches) = 512 blocks
    hamming_kernel<<<grid, TPB, SMEM_TOTAL>>>(x, w_self, w_bits, mix_w, mix_b, out);
}

// round 17
// speedup vs baseline: 1.1957x; 1.1957x over previous
#include <cuda_runtime.h>
#include <cuda_bf16.h>
#include <cstdint>

// Hamming1Layer v14: v10 (best, 76.3us) with CHUNK_L=256 -> half the barriers,
// 2x gather MLP window, 2 mix tiles per warp per chunk. All else identical.
// y[b,c,l] = (w_self*x[b,c,l] + sum_k w_bits[k]*x[b,c,l^(1<<k)]) / 15
// out[b,o,l] = sum_c mix_w[o,c]*y[b,c,l] + mix_b[o]
// B=32, C_IN=32, C_OUT=64, L=16384, N_BITS=14.
// Split MMA: D = Wh.Yh + Wh.Yl + Wl.Yh (bf16, fp32 accum).

#define NBITS   14
#define LPOW    16384
#define CIN     32
#define COUT    64
#define TILE_L  512
#define CHUNK_L 256
#define NCHUNK  (TILE_L / CHUNK_L)     // 2
#define CQUADS  (CHUNK_L / 4)          // 64
#define TPB     256

// ---- smem map (bytes) ----
#define YROW    264                    // bf16 elems per y row (256 + 8 pad; 528B stride -> distinct banks)
#define WROW    40                     // bf16 elems per W row (32 + 8 pad)
#define YSPLIT  (CIN * YROW * 2)       // 16896
#define YBUF    (2 * YSPLIT)           // h + l planes = 33792
#define SMEM_XB    0                   // bf16 [CIN][TILE_L]       = 32768
#define SMEM_Y     32768               // [2 buf][h/l][CIN][YROW]  = 67584
#define SMEM_WH    100352              // bf16 [COUT][WROW] = 5120
#define SMEM_WL    105472              // bf16 [COUT][WROW] = 5120
#define SMEM_BIAS  110592              // f32 [COUT] = 256
#define SMEM_TOTAL 110848              // x2 = 216.5KiB -> 2 blocks/SM

__device__ __forceinline__ uint64_t pack2(float lo, float hi) {
    uint64_t r; asm("mov.b64 %0, {%1, %2};" : "=l"(r) : "f"(lo), "f"(hi)); return r;
}
__device__ __forceinline__ void unpack2(uint64_t v, float& lo, float& hi) {
    asm("mov.b64 {%0, %1}, %2;" : "=f"(lo), "=f"(hi) : "l"(v));
}
__device__ __forceinline__ uint64_t fma2(uint64_t a, uint64_t b, uint64_t c) {
    uint64_t d; asm("fma.rn.f32x2 %0, %1, %2, %3;" : "=l"(d) : "l"(a), "l"(b), "l"(c)); return d;
}
__device__ __forceinline__ uint64_t mul2(uint64_t a, uint64_t b) {
    uint64_t d; asm("mul.rn.f32x2 %0, %1, %2;" : "=l"(d) : "l"(a), "l"(b)); return d;
}
__device__ __forceinline__ uint64_t add2(uint64_t a, uint64_t b) {
    uint64_t d; asm("add.rn.f32x2 %0, %1, %2;" : "=l"(d) : "l"(a), "l"(b)); return d;
}
__device__ __forceinline__ uint64_t sub2(uint64_t a, uint64_t b) {
    uint64_t d; asm("sub.rn.f32x2 %0, %1, %2;" : "=l"(d) : "l"(a), "l"(b)); return d;
}
__device__ __forceinline__ uint64_t bfp_to_f32x2(uint32_t v) {
    uint32_t lo = v << 16, hi = v & 0xFFFF0000u;
    uint64_t r; asm("mov.b64 %0, {%1, %2};" : "=l"(r) : "r"(lo), "r"(hi)); return r;
}
__device__ __forceinline__ uint32_t f2_to_bfp(float a, float b) {
    uint32_t r; asm("cvt.rn.bf16x2.f32 %0, %1, %2;" : "=r"(r) : "f"(b), "f"(a)); return r;
}

#define LDSM_X4_T(d, addr)                                                      \
    asm volatile("ldmatrix.sync.aligned.m8n8.x4.trans.shared.b16 "              \
                 "{%0,%1,%2,%3}, [%4];"                                         \
                 : "=r"((d)[0]), "=r"((d)[1]), "=r"((d)[2]), "=r"((d)[3])       \
                 : "r"(addr))
#define LDSM_X2(d0, d1, addr)                                                   \
    asm volatile("ldmatrix.sync.aligned.m8n8.x2.shared.b16 {%0,%1}, [%2];"      \
                 : "=r"(d0), "=r"(d1) : "r"(addr))
#define MMA_BF16(c, a, b0, b1)                                                  \
    asm volatile("mma.sync.aligned.m16n8k16.row.col.f32.bf16.bf16.f32 "         \
                 "{%0,%1,%2,%3}, {%4,%5,%6,%7}, {%8,%9}, {%0,%1,%2,%3};"        \
                 : "+f"((c)[0]), "+f"((c)[1]), "+f"((c)[2]), "+f"((c)[3])       \
                 : "r"((a)[0]), "r"((a)[1]), "r"((a)[2]), "r"((a)[3]),          \
                   "r"(b0), "r"(b1))

extern __shared__ unsigned char smem_raw[];

__global__ __launch_bounds__(TPB, 2)
void hamming_kernel(const float* __restrict__ x,
                    const float* __restrict__ w_self,
                    const float* __restrict__ w_bits,
                    const float* __restrict__ mix_w,
                    const float* __restrict__ mix_b,
                    float* __restrict__ out)
{
    uint32_t*      sh_xb   = (uint32_t*)(smem_raw + SMEM_XB);
    __nv_bfloat16* sh_wh   = (__nv_bfloat16*)(smem_raw + SMEM_WH);
    __nv_bfloat16* sh_wl   = (__nv_bfloat16*)(smem_raw + SMEM_WL);
    float*         sh_bias = (float*)(smem_raw + SMEM_BIAS);
    const uint32_t sbase   = (uint32_t)__cvta_generic_to_shared(smem_raw);

    const int tid   = threadIdx.x;
    const int wid   = tid >> 5;
    const int lane  = tid & 31;
    const int tile  = blockIdx.x;            // 0..31
    const int b     = blockIdx.y;            // 0..31
    const int lbase = tile * TILE_L;

    // ---- cooperative staging ----
    const float inv15 = 1.0f / 15.0f;
    for (int e = tid; e < CIN * COUT; e += TPB) {   // e = o*32 + c
        int o = e >> 5, c = e & 31;
        float w = mix_w[e] * inv15;
        __nv_bfloat16 wh = __float2bfloat16(w);
        sh_wh[o * WROW + c] = wh;
        sh_wl[o * WROW + c] = __float2bfloat16(w - __bfloat162float(wh));
    }
    if (tid < COUT) sh_bias[tid] = mix_b[tid];

    const float4* xg4 = (const float4*)(x + (size_t)b * CIN * LPOW);
    #pragma unroll
    for (int i = 0; i < (CIN * TILE_L / 4) / TPB; ++i) {    // 16 iters
        int j  = i * TPB + tid;
        int c  = j >> 7;                 // 128 float4 per c
        int lw = j & 127;
        float4 f = xg4[(size_t)c * (LPOW / 4) + (lbase >> 2) + lw];
        uint2 p; p.x = f2_to_bfp(f.x, f.y); p.y = f2_to_bfp(f.z, f.w);
        *(uint2*)(sh_xb + c * (TILE_L / 2) + lw * 2) = p;
    }

    // ---- per-thread gather weights ----
    const float ws = *w_self;
    const uint64_t ws2 = pack2(ws, ws);
    uint64_t wb2[NBITS];
    #pragma unroll
    for (int k = 0; k < NBITS; ++k) { float v = w_bits[k]; wb2[k] = pack2(v, v); }

    // ---- mix-stage lane constants ----
    const int g = lane >> 2, t = lane & 3;
    const int krow0 = (lane & 7) + ((lane >> 4) & 1) * 8;
    const int mcolA = ((lane >> 3) & 1) * 8;
    const int brow  = lane & 7;
    const int bk    = ((lane >> 3) & 1) * 8;
    const uint32_t whB = sbase + SMEM_WH;
    const uint32_t wlB = sbase + SMEM_WL;

    const float* xb = x + (size_t)b * CIN * LPOW;
    float* og = out + (size_t)b * COUT * LPOW;

    __syncthreads();

    for (int ck = 0; ck < NCHUNK; ++ck) {
        // ================= gather (all 256 threads, 8 items) =================
        unsigned char* ybh_w = smem_raw + SMEM_Y + (ck & 1) * YBUF;
        unsigned char* ybl_w = ybh_w + YSPLIT;

        #pragma unroll
        for (int it = 0; it < (CIN * CQUADS) / TPB; ++it) {   // 8 iters
            int idx = it * TPB + tid;
            int c   = idx >> 6;              // 0..31 (64 quads per c)
            int ql  = idx & 63;              // quad in chunk
            int qg  = ck * CQUADS + ql;      // quad in tile [0,128)

            const float4*   xc4 = (const float4*)(xb + (size_t)c * LPOW);
            const uint32_t* row = sh_xb + c * (TILE_L / 2);

            // remote (L2-latency) loads first; L1-hot self last
            float4 g9  = xc4[((lbase ^ (1 <<  9)) >> 2) + qg];
            float4 g10 = xc4[((lbase ^ (1 << 10)) >> 2) + qg];
            float4 g11 = xc4[((lbase ^ (1 << 11)) >> 2) + qg];
            float4 g12 = xc4[((lbase ^ (1 << 12)) >> 2) + qg];
            float4 g13 = xc4[((lbase ^ (1 << 13)) >> 2) + qg];
            float4 s   = xc4[(lbase >> 2) + qg];

            uint64_t s01 = pack2(s.x, s.y), s23 = pack2(s.z, s.w);
            uint64_t a01 = mul2(ws2, s01);
            uint64_t a23 = mul2(ws2, s23);
            a01 = fma2(wb2[0], pack2(s.y, s.x), a01);
            a23 = fma2(wb2[0], pack2(s.w, s.z), a23);
            a01 = fma2(wb2[1], s23, a01);
            a23 = fma2(wb2[1], s01, a23);

            // bits 2..8: bf16 quads from SMEM tile
            uint64_t b01, b23;
            {
                uint2 n = *(const uint2*)(row + (qg ^ 1) * 2);
                b01 = mul2(wb2[2], bfp_to_f32x2(n.x));
                b23 = mul2(wb2[2], bfp_to_f32x2(n.y));
            }
            #pragma unroll
            for (int k = 3; k <= 8; ++k) {
                int qn = qg ^ (1 << (k - 2));
                uint2 n = *(const uint2*)(row + qn * 2);
                b01 = fma2(wb2[k], bfp_to_f32x2(n.x), b01);
                b23 = fma2(wb2[k], bfp_to_f32x2(n.y), b23);
            }

            // bits 9..13: f32 quads from global (L2-hot)
            a01 = fma2(wb2[ 9], pack2(g9.x,  g9.y),  a01);
            a23 = fma2(wb2[ 9], pack2(g9.z,  g9.w),  a23);
            a01 = fma2(wb2[10], pack2(g10.x, g10.y), a01);
            a23 = fma2(wb2[10], pack2(g10.z, g10.w), a23);
            a01 = fma2(wb2[11], pack2(g11.x, g11.y), a01);
            a23 = fma2(wb2[11], pack2(g11.z, g11.w), a23);
            a01 = fma2(wb2[12], pack2(g12.x, g12.y), a01);
            a23 = fma2(wb2[12], pack2(g12.z, g12.w), a23);
            a01 = fma2(wb2[13], pack2(g13.x, g13.y), a01);
            a23 = fma2(wb2[13], pack2(g13.z, g13.w), a23);

            a01 = add2(a01, b01);
            a23 = add2(a23, b23);

            // split y -> bf16 hi/lo planes, layout [c][l] padded to YROW
            float y0, y1, y2, y3;
            unpack2(a01, y0, y1);
            unpack2(a23, y2, y3);
            uint32_t hA = f2_to_bfp(y0, y1);
            uint32_t hB = f2_to_bfp(y2, y3);
            uint64_t r01 = sub2(a01, bfp_to_f32x2(hA));
            uint64_t r23 = sub2(a23, bfp_to_f32x2(hB));
            float r0, r1, r2, r3;
            unpack2(r01, r0, r1);
            unpack2(r23, r2, r3);
            uint32_t lA = f2_to_bfp(r0, r1);
            uint32_t lB = f2_to_bfp(r2, r3);

            int yoff = c * (YROW * 2) + ql * 8;      // bytes
            *(uint2*)(ybh_w + yoff) = make_uint2(hA, hB);
            *(uint2*)(ybl_w + yoff) = make_uint2(lA, lB);
        }
        __syncthreads();    // chunk ck y ready; mixing of ck-1 finished

        // ========= mix (8 warps, 2 m16 tiles each = 16 tiles / 256 l) =========
        const uint32_t ybh = sbase + SMEM_Y + (ck & 1) * YBUF;
        const uint32_t ybl = ybh + YSPLIT;

        #pragma unroll
        for (int j = 0; j < 2; ++j) {
            const int wbase = (wid * 2 + j) * 16;    // l rows in chunk [0,256)

            uint32_t Ah[2][4], Al[2][4];
            #pragma unroll
            for (int ks = 0; ks < 2; ++ks) {
                uint32_t off = (uint32_t)(((ks * 16 + krow0) * YROW + wbase + mcolA) * 2);
                LDSM_X4_T(Ah[ks], ybh + off);
                LDSM_X4_T(Al[ks], ybl + off);
            }

            float acc[8][4];
            #pragma unroll
            for (int nt = 0; nt < 8; ++nt) {
                float2 bb = *(float2*)(sh_bias + nt * 8 + 2 * t);
                acc[nt][0] = bb.x; acc[nt][1] = bb.y;
                acc[nt][2] = bb.x; acc[nt][3] = bb.y;
            }

            #pragma unroll
            for (int ks = 0; ks < 2; ++ks) {
                #pragma unroll
                for (int nt = 0; nt < 8; ++nt) {
                    uint32_t woff = (uint32_t)(((nt * 8 + brow) * WROW + ks * 16 + bk) * 2);
                    uint32_t bh0, bh1, bl0, bl1;
                    LDSM_X2(bh0, bh1, whB + woff);
                    MMA_BF16(acc[nt], Ah[ks], bh0, bh1);   // Wh.Yh
                    MMA_BF16(acc[nt], Al[ks], bh0, bh1);   // Wh.Yl
                    LDSM_X2(bl0, bl1, wlB + woff);
                    MMA_BF16(acc[nt], Ah[ks], bl0, bl1);   // Wl.Yh
                }
            }

            // epilogue: D[m=l][n=o] -> out[b][o][l]; c2/c3 live at row m+8
            const int l0 = lbase + ck * CHUNK_L + wbase + g;
            #pragma unroll
            for (int nt = 0; nt < 8; ++nt) {
                int o0 = nt * 8 + 2 * t;
                og[(size_t)o0 * LPOW + l0]            = acc[nt][0];
                og[(size_t)(o0 + 1) * LPOW + l0]      = acc[nt][1];
                og[(size_t)o0 * LPOW + l0 + 8]        = acc[nt][2];
                og[(size_t)(o0 + 1) * LPOW + l0 + 8]  = acc[nt][3];
            }
        }
    }
}

extern "C" void kernel_launch(void* const* d_in, const int* in_sizes, int n_in,
                              void* d_out, int out_size)
{
    const float* x      = (const float*)d_in[0];
    const float* w_self = (const float*)d_in[1];
    const float* w_bits = (const float*)d_in[2];
    const float* mix_w  = (const float*)d_in[3];
    const float* mix_b  = (const float*)d_in[4];
    float* out = (float*)d_out;

    cudaFuncSetAttribute(hamming_kernel,
                         cudaFuncAttributeMaxDynamicSharedMemorySize, SMEM_TOTAL);

    dim3 grid(LPOW / TILE_L, 32, 1);   // (32 tiles, 32 batches) = 1024 blocks
    hamming_kernel<<<grid, TPB, SMEM_TOTAL>>>(x, w_self, w_bits, mix_w, mix_b, out);
}